// round 10
// baseline (speedup 1.0000x reference)
#include <cuda_runtime.h>
#include <cuda_bf16.h>

// Problem constants (from reference)
#define BATCH  16
#define MCTRL  64
#define NCTRL  64
#define LKNOT  68      // M + P + 1
#define DEG    3
#define TOUT   256     // OUT_U == OUT_V
#define RPB    4       // u-rows per block
#define THREADS 256
#define BPB    (TOUT / RPB)   // 64 blocks per batch
#define UPAD   (LKNOT + 28)   // padded knots for branch-free bsearch

// Span binary search on padded array (U[i>=LKNOT] = +inf): reference's
// first-occurrence argmin over masked diffs equals the last index s with
// (traw - U[s+DEG] > thr), or 0 if none.
__device__ __forceinline__ int find_span(const float* __restrict__ U,
                                         float traw, float thr)
{
    int c = 0;
    #pragma unroll
    for (int step = 32; step >= 1; step >>= 1) {
        int nc = c + step;
        if ((traw - U[nc - 1 + DEG]) > thr) c = nc;   // pad => pred false
    }
    if (c > 62) c = 62;
    int bi = c - 1;
    if (bi < 0) bi = 0;
    int span = bi + DEG;
    if (span > MCTRL - 1) span = MCTRL - 1;
    return span;
}

// Degree-3 Cox-de Boor on raw (unnormalized) knots — affine invariant.
__device__ __forceinline__ float4 cox_de_boor(const float* __restrict__ U,
                                              float t, int span)
{
    float Nb[DEG + 1];
    Nb[0] = 1.f;
    #pragma unroll
    for (int k = 1; k <= DEG; k++) {
        float saved = 0.f;
        #pragma unroll
        for (int r = 0; r < DEG; r++) {
            if (r >= k) break;
            float K1   = U[span + r + 1];
            float K2   = U[span + 1 - k + r];
            float temp = __fdividef(Nb[r], (K1 - t) + (t - K2));
            Nb[r]  = saved + (K1 - t) * temp;
            saved  = (t - K2) * temp;
        }
        Nb[k] = saved;
    }
    return make_float4(Nb[0], Nb[1], Nb[2], Nb[3]);
}

// ---------------------------------------------------------------------------
// Fused kernel. 256 threads, 4 u-rows per block, 1024 blocks, single launch.
//  - one Cox-de Boor per thread (own column), shared via basis_sh/span_sh
//  - row span recomputed cheaply pre-barrier so ctrl LDGs fly early
//  - phase 2: thread = (row, 4-column group) -> 3x STG.128 per thread-row
// u and v parameter grids are identical (reference builds V from knot_u too).
// ---------------------------------------------------------------------------
__global__ __launch_bounds__(THREADS, 6) void SurfEval_fused_kernel(
    const float4* __restrict__ ctrl,   // [B][64][64] float4 (x,y,z,w)
    const float*  __restrict__ knot_u, // [B][68]
    float*        __restrict__ out)    // [B][256][256][3]
{
    const int b    = blockIdx.x / BPB;
    const int i0   = (blockIdx.x % BPB) * RPB;
    const int tid  = threadIdx.x;
    const int lane = tid & 31;
    const int wid  = tid >> 5;

    __shared__ float  U[UPAD];
    __shared__ float  warpsum[2];
    __shared__ float4 basis_sh[TOUT];                       // 4 KB
    __shared__ __align__(4) unsigned char span_sh[TOUT];    // 256 B (span-3)
    __shared__ float4 cols4[RPB][NCTRL];                    // 4 KB

    // ---- parallel inclusive cumsum of the 68 raw knot increments ----
    {
        float v = (tid < LKNOT) ? knot_u[b * LKNOT + tid] : 0.f;
        #pragma unroll
        for (int off = 1; off < 32; off <<= 1) {
            float n = __shfl_up_sync(0xffffffffu, v, off);
            if (lane >= off) v += n;
        }
        if (lane == 31 && wid < 2) warpsum[wid] = v;
        if (tid >= LKNOT && tid < UPAD) U[tid] = __int_as_float(0x7f800000);
        __syncthreads();
        if (wid == 1)      v += warpsum[0];
        else if (wid == 2) v += warpsum[0] + warpsum[1];
        if (tid < LKNOT) U[tid] = v;
        __syncthreads();
    }

    const float c0  = U[0];
    const float den = U[LKNOT - 1] - c0;
    const float thr = 1e-8f * den;
    const float step01 = (float)((1.0 - 2e-5) / 255.0);

    // ---- row span (cheap recompute) -> issue ctrl loads ASAP ----
    const int ri = tid >> 6;            // 0..3
    const int cc = tid & 63;            // 0..63
    const int i  = i0 + ri;

    const float t_row = c0 + fmaf((float)i, step01, 1e-5f) * den;
    const int   srow  = find_span(U, t_row, thr) - 3;

    const float4* cp = ctrl + ((size_t)(b * MCTRL) + srow) * NCTRL + cc;
    float4 p0 = cp[0 * NCTRL];
    float4 p1 = cp[1 * NCTRL];
    float4 p2 = cp[2 * NCTRL];
    float4 p3 = cp[3 * NCTRL];

    // ---- own span + basis (only cox in the kernel), publish ----
    {
        const float t_own = c0 + fmaf((float)tid, step01, 1e-5f) * den;
        const int   so    = find_span(U, t_own, thr);
        basis_sh[tid] = cox_de_boor(U, t_own, so);
        span_sh[tid]  = (unsigned char)(so - 3);
    }
    __syncthreads();   // basis publish (ctrl loads still in flight)

    // ---- phase 1: u-contraction for (row ri, ctrl column cc) ----
    {
        const float4 nu = basis_sh[i];
        float4 r;
        r.x = fmaf(nu.x, p0.x, fmaf(nu.y, p1.x, fmaf(nu.z, p2.x, nu.w * p3.x)));
        r.y = fmaf(nu.x, p0.y, fmaf(nu.y, p1.y, fmaf(nu.z, p2.y, nu.w * p3.y)));
        r.z = fmaf(nu.x, p0.z, fmaf(nu.y, p1.z, fmaf(nu.z, p2.z, nu.w * p3.z)));
        r.w = 0.f;
        cols4[ri][cc] = r;
    }
    __syncthreads();   // cols publish

    // ---- phase 2: thread = (row r, column group g): columns 4g..4g+3 ----
    {
        const int r = tid >> 6;         // 0..3
        const int g = tid & 63;         // 0..63

        const unsigned int sp4 =
            *reinterpret_cast<const unsigned int*>(span_sh + 4 * g);

        float o[12];
        #pragma unroll
        for (int c = 0; c < 4; c++) {
            const int    sj = (int)((sp4 >> (8 * c)) & 0xffu);
            const float4 nv = basis_sh[4 * g + c];
            const float4 a  = cols4[r][sj];
            const float4 bb = cols4[r][sj + 1];
            const float4 cq = cols4[r][sj + 2];
            const float4 d  = cols4[r][sj + 3];

            o[3 * c + 0] = fmaf(nv.x, a.x, fmaf(nv.y, bb.x, fmaf(nv.z, cq.x, nv.w * d.x)));
            o[3 * c + 1] = fmaf(nv.x, a.y, fmaf(nv.y, bb.y, fmaf(nv.z, cq.y, nv.w * d.y)));
            o[3 * c + 2] = fmaf(nv.x, a.z, fmaf(nv.y, bb.z, fmaf(nv.z, cq.z, nv.w * d.z)));
        }

        // 48 contiguous bytes -> 3x STG.128 (16B-aligned: 48g % 16 == 0)
        float4* op = reinterpret_cast<float4*>(
            out + ((size_t)((b * TOUT) + i0 + r) * TOUT + 4 * g) * 3);
        op[0] = make_float4(o[0], o[1], o[2],  o[3]);
        op[1] = make_float4(o[4], o[5], o[6],  o[7]);
        op[2] = make_float4(o[8], o[9], o[10], o[11]);
    }
}

// ---------------------------------------------------------------------------
// Launch. Inputs: d_in[0]=ctrl_pts [16,64,64,4] f32, d_in[1]=knot_u [16,68],
// d_in[2]=knot_v (UNUSED — reference builds V from knot_u).
// Output: [16,256,256,3] f32.
// ---------------------------------------------------------------------------
extern "C" void kernel_launch(void* const* d_in, const int* in_sizes, int n_in,
                              void* d_out, int out_size)
{
    const float4* ctrl   = (const float4*)d_in[0];
    const float*  knot_u = (const float*) d_in[1];
    float*        out    = (float*)d_out;

    SurfEval_fused_kernel<<<BATCH * BPB, THREADS>>>(ctrl, knot_u, out);
}

// round 11
// speedup vs baseline: 1.1831x; 1.1831x over previous
#include <cuda_runtime.h>
#include <cuda_bf16.h>

// Problem constants (from reference)
#define BATCH  16
#define MCTRL  64
#define NCTRL  64
#define LKNOT  68      // M + P + 1
#define DEG    3
#define TOUT   256     // OUT_U == OUT_V
#define RPB    4       // u-rows per block
#define THREADS 256
#define BPB    (TOUT / RPB)   // 64 blocks per batch
#define UPAD   (LKNOT + 28)   // padded knots for branch-free bsearch

// Span binary search on padded array (U[i>=LKNOT] = +inf): reference's
// first-occurrence argmin over masked diffs equals the last index s with
// (traw - U[s+DEG] > thr), or 0 if none.
__device__ __forceinline__ int find_span(const float* __restrict__ U,
                                         float traw, float thr)
{
    int c = 0;
    #pragma unroll
    for (int step = 32; step >= 1; step >>= 1) {
        int nc = c + step;
        if ((traw - U[nc - 1 + DEG]) > thr) c = nc;   // pad => pred false
    }
    if (c > 62) c = 62;
    int bi = c - 1;
    if (bi < 0) bi = 0;
    int span = bi + DEG;
    if (span > MCTRL - 1) span = MCTRL - 1;
    return span;
}

// Degree-3 Cox-de Boor on raw (unnormalized) knots — affine invariant.
// __fdividef: tolerance is 1e-3, current margin ~400x.
__device__ __forceinline__ float4 cox_de_boor(const float* __restrict__ U,
                                              float t, int span)
{
    float Nb[DEG + 1];
    Nb[0] = 1.f;
    #pragma unroll
    for (int k = 1; k <= DEG; k++) {
        float saved = 0.f;
        #pragma unroll
        for (int r = 0; r < DEG; r++) {
            if (r >= k) break;
            float K1   = U[span + r + 1];
            float K2   = U[span + 1 - k + r];
            float temp = __fdividef(Nb[r], (K1 - t) + (t - K2));
            Nb[r]  = saved + (K1 - t) * temp;
            saved  = (t - K2) * temp;
        }
        Nb[k] = saved;
    }
    return make_float4(Nb[0], Nb[1], Nb[2], Nb[3]);
}

// ---------------------------------------------------------------------------
// Fused kernel (R7 structure, best so far), streaming stores.
// 256 threads, 4 u-rows per block, 1024 blocks, single launch, one cox per
// thread for its own column + cheap row-span recompute so ctrl LDGs fly early.
// u and v parameter grids are identical (reference builds V from knot_u too).
// ---------------------------------------------------------------------------
__global__ __launch_bounds__(THREADS, 8) void SurfEval_fused_kernel(
    const float4* __restrict__ ctrl,   // [B][64][64] float4 (x,y,z,w)
    const float*  __restrict__ knot_u, // [B][68]
    float*        __restrict__ out)    // [B][256][256][3]
{
    const int b    = blockIdx.x / BPB;
    const int i0   = (blockIdx.x % BPB) * RPB;
    const int tid  = threadIdx.x;
    const int lane = tid & 31;
    const int wid  = tid >> 5;

    __shared__ float  U[UPAD];
    __shared__ float  warpsum[2];
    __shared__ float4 cols4[RPB][NCTRL];   // 4 KB: (x,y,z,pad) u-contracted

    // ---- parallel inclusive cumsum of the 68 raw knot increments ----
    {
        float v = (tid < LKNOT) ? knot_u[b * LKNOT + tid] : 0.f;
        #pragma unroll
        for (int off = 1; off < 32; off <<= 1) {
            float n = __shfl_up_sync(0xffffffffu, v, off);
            if (lane >= off) v += n;
        }
        if (lane == 31 && wid < 2) warpsum[wid] = v;
        if (tid >= LKNOT && tid < UPAD) U[tid] = __int_as_float(0x7f800000);
        __syncthreads();
        if (wid == 1)      v += warpsum[0];
        else if (wid == 2) v += warpsum[0] + warpsum[1];
        if (tid < LKNOT) U[tid] = v;
        __syncthreads();
    }

    const float c0  = U[0];
    const float den = U[LKNOT - 1] - c0;
    const float thr = 1e-8f * den;
    const float step01 = (float)((1.0 - 2e-5) / 255.0);

    // ---- phase 1: rows i0..i0+3, thread = (row, ctrl column) ----
    const int ri = tid >> 6;            // 0..3
    const int cc = tid & 63;            // 0..63
    {
        const int   i     = i0 + ri;
        const float t_row = c0 + fmaf((float)i, step01, 1e-5f) * den;
        const int   srow  = find_span(U, t_row, thr);

        const float4* cp = ctrl + ((size_t)(b * MCTRL) + (srow - 3)) * NCTRL + cc;
        float4 p0 = cp[0 * NCTRL];
        float4 p1 = cp[1 * NCTRL];
        float4 p2 = cp[2 * NCTRL];
        float4 p3 = cp[3 * NCTRL];

        const float4 nu = cox_de_boor(U, t_row, srow);   // overlaps loads
        float4 r;
        r.x = fmaf(nu.x, p0.x, fmaf(nu.y, p1.x, fmaf(nu.z, p2.x, nu.w * p3.x)));
        r.y = fmaf(nu.x, p0.y, fmaf(nu.y, p1.y, fmaf(nu.z, p2.y, nu.w * p3.y)));
        r.z = fmaf(nu.x, p0.z, fmaf(nu.y, p1.z, fmaf(nu.z, p2.z, nu.w * p3.z)));
        r.w = 0.f;
        cols4[ri][cc] = r;
    }

    // ---- own (v-role) span + basis for output column j = tid ----
    const int   j     = tid;
    const float t_own = c0 + fmaf((float)j, step01, 1e-5f) * den;
    const int   sj    = find_span(U, t_own, thr) - 3;
    const float4 nv   = cox_de_boor(U, t_own, sj + 3);

    __syncthreads();   // single post-scan barrier: cols publish

    // ---- phase 2: v-contraction, RPB independent rows per thread ----
    // Streaming stores (evict-first): output is never re-read by this kernel,
    // so avoid L1 allocation for the 12 stride-12 STG.32 per thread.
    float* o = out + ((size_t)((b * TOUT) + i0) * TOUT + j) * 3;
    #pragma unroll
    for (int r = 0; r < RPB; r++) {
        float4 a  = cols4[r][sj];
        float4 bb = cols4[r][sj + 1];
        float4 cq = cols4[r][sj + 2];
        float4 d  = cols4[r][sj + 3];

        float x = fmaf(nv.x, a.x, fmaf(nv.y, bb.x, fmaf(nv.z, cq.x, nv.w * d.x)));
        float y = fmaf(nv.x, a.y, fmaf(nv.y, bb.y, fmaf(nv.z, cq.y, nv.w * d.y)));
        float z = fmaf(nv.x, a.z, fmaf(nv.y, bb.z, fmaf(nv.z, cq.z, nv.w * d.z)));

        __stcs(o + 0, x);
        __stcs(o + 1, y);
        __stcs(o + 2, z);
        o += (size_t)TOUT * 3;   // next row
    }
}

// ---------------------------------------------------------------------------
// Launch. Inputs: d_in[0]=ctrl_pts [16,64,64,4] f32, d_in[1]=knot_u [16,68],
// d_in[2]=knot_v (UNUSED — reference builds V from knot_u).
// Output: [16,256,256,3] f32.
// ---------------------------------------------------------------------------
extern "C" void kernel_launch(void* const* d_in, const int* in_sizes, int n_in,
                              void* d_out, int out_size)
{
    const float4* ctrl   = (const float4*)d_in[0];
    const float*  knot_u = (const float*) d_in[1];
    float*        out    = (float*)d_out;

    SurfEval_fused_kernel<<<BATCH * BPB, THREADS>>>(ctrl, knot_u, out);
}

// round 12
// speedup vs baseline: 1.2113x; 1.0238x over previous
#include <cuda_runtime.h>
#include <cuda_bf16.h>

// Problem constants (from reference)
#define BATCH  16
#define MCTRL  64
#define NCTRL  64
#define LKNOT  68      // M + P + 1
#define DEG    3
#define TOUT   256     // OUT_U == OUT_V
#define RPB    4       // u-rows per block
#define THREADS 256
#define BPB    (TOUT / RPB)   // 64 blocks per batch
#define UPAD   (LKNOT + 28)   // padded knots for branch-free bsearch

// Span binary search on padded array (U[i>=LKNOT] = +inf): reference's
// first-occurrence argmin over masked diffs equals the last index s with
// (traw - U[s+DEG] > thr), or 0 if none.
__device__ __forceinline__ int find_span(const float* __restrict__ U,
                                         float traw, float thr)
{
    int c = 0;
    #pragma unroll
    for (int step = 32; step >= 1; step >>= 1) {
        int nc = c + step;
        if ((traw - U[nc - 1 + DEG]) > thr) c = nc;   // pad => pred false
    }
    if (c > 62) c = 62;
    int bi = c - 1;
    if (bi < 0) bi = 0;
    int span = bi + DEG;
    if (span > MCTRL - 1) span = MCTRL - 1;
    return span;
}

// Degree-3 Cox-de Boor on raw (unnormalized) knots — affine invariant.
// __fdividef: tolerance is 1e-3, current margin ~400x.
__device__ __forceinline__ float4 cox_de_boor(const float* __restrict__ U,
                                              float t, int span)
{
    float Nb[DEG + 1];
    Nb[0] = 1.f;
    #pragma unroll
    for (int k = 1; k <= DEG; k++) {
        float saved = 0.f;
        #pragma unroll
        for (int r = 0; r < DEG; r++) {
            if (r >= k) break;
            float K1   = U[span + r + 1];
            float K2   = U[span + 1 - k + r];
            float temp = __fdividef(Nb[r], (K1 - t) + (t - K2));
            Nb[r]  = saved + (K1 - t) * temp;
            saved  = (t - K2) * temp;
        }
        Nb[k] = saved;
    }
    return make_float4(Nb[0], Nb[1], Nb[2], Nb[3]);
}

// ---------------------------------------------------------------------------
// Fused kernel, single-cox variant of the best (R7) structure.
// 256 threads, 4 u-rows per block, 1024 blocks, single launch.
// Each thread runs Cox-de Boor ONCE (its own column) and publishes it;
// phase 1 reads the row basis via a warp-uniform broadcast LDS. The row
// span is still recomputed cheaply pre-barrier so the ctrl LDG.128s issue
// before the cox compute and stay in flight across the publish barrier.
// u and v parameter grids are identical (reference builds V from knot_u too).
// ---------------------------------------------------------------------------
__global__ __launch_bounds__(THREADS, 8) void SurfEval_fused_kernel(
    const float4* __restrict__ ctrl,   // [B][64][64] float4 (x,y,z,w)
    const float*  __restrict__ knot_u, // [B][68]
    float*        __restrict__ out)    // [B][256][256][3]
{
    const int b    = blockIdx.x / BPB;
    const int i0   = (blockIdx.x % BPB) * RPB;
    const int tid  = threadIdx.x;
    const int lane = tid & 31;
    const int wid  = tid >> 5;

    __shared__ float  U[UPAD];
    __shared__ float  warpsum[2];
    __shared__ float4 basis_sh[TOUT];      // 4 KB (only rows i0..i0+3 re-read)
    __shared__ float4 cols4[RPB][NCTRL];   // 4 KB: (x,y,z,pad) u-contracted

    // ---- parallel inclusive cumsum of the 68 raw knot increments ----
    {
        float v = (tid < LKNOT) ? knot_u[b * LKNOT + tid] : 0.f;
        #pragma unroll
        for (int off = 1; off < 32; off <<= 1) {
            float n = __shfl_up_sync(0xffffffffu, v, off);
            if (lane >= off) v += n;
        }
        if (lane == 31 && wid < 2) warpsum[wid] = v;
        if (tid >= LKNOT && tid < UPAD) U[tid] = __int_as_float(0x7f800000);
        __syncthreads();
        if (wid == 1)      v += warpsum[0];
        else if (wid == 2) v += warpsum[0] + warpsum[1];
        if (tid < LKNOT) U[tid] = v;
        __syncthreads();
    }

    const float c0  = U[0];
    const float den = U[LKNOT - 1] - c0;
    const float thr = 1e-8f * den;
    const float step01 = (float)((1.0 - 2e-5) / 255.0);

    // ---- row span (cheap recompute) -> issue ctrl loads ASAP ----
    const int ri = tid >> 6;            // 0..3
    const int cc = tid & 63;            // 0..63
    const int i  = i0 + ri;

    const float t_row = c0 + fmaf((float)i, step01, 1e-5f) * den;
    const int   srow  = find_span(U, t_row, thr) - 3;

    const float4* cp = ctrl + ((size_t)(b * MCTRL) + srow) * NCTRL + cc;
    float4 p0 = cp[0 * NCTRL];
    float4 p1 = cp[1 * NCTRL];
    float4 p2 = cp[2 * NCTRL];
    float4 p3 = cp[3 * NCTRL];

    // ---- own (v-role) span + basis: the ONLY cox in the kernel ----
    const int   j     = tid;
    const float t_own = c0 + fmaf((float)j, step01, 1e-5f) * den;
    const int   sj    = find_span(U, t_own, thr) - 3;
    const float4 nv   = cox_de_boor(U, t_own, sj + 3);

    basis_sh[tid] = nv;
    __syncthreads();   // basis publish (ctrl loads still in flight)

    // ---- phase 1: u-contraction for (row ri, ctrl column cc) ----
    {
        const float4 nu = basis_sh[i];   // warp-uniform -> broadcast LDS
        float4 r;
        r.x = fmaf(nu.x, p0.x, fmaf(nu.y, p1.x, fmaf(nu.z, p2.x, nu.w * p3.x)));
        r.y = fmaf(nu.x, p0.y, fmaf(nu.y, p1.y, fmaf(nu.z, p2.y, nu.w * p3.y)));
        r.z = fmaf(nu.x, p0.z, fmaf(nu.y, p1.z, fmaf(nu.z, p2.z, nu.w * p3.z)));
        r.w = 0.f;
        cols4[ri][cc] = r;
    }
    __syncthreads();   // cols publish

    // ---- phase 2: v-contraction, RPB independent rows per thread ----
    float* o = out + ((size_t)((b * TOUT) + i0) * TOUT + j) * 3;
    #pragma unroll
    for (int r = 0; r < RPB; r++) {
        float4 a  = cols4[r][sj];
        float4 bb = cols4[r][sj + 1];
        float4 cq = cols4[r][sj + 2];
        float4 d  = cols4[r][sj + 3];

        float x = fmaf(nv.x, a.x, fmaf(nv.y, bb.x, fmaf(nv.z, cq.x, nv.w * d.x)));
        float y = fmaf(nv.x, a.y, fmaf(nv.y, bb.y, fmaf(nv.z, cq.y, nv.w * d.y)));
        float z = fmaf(nv.x, a.z, fmaf(nv.y, bb.z, fmaf(nv.z, cq.z, nv.w * d.z)));

        __stcs(o + 0, x);
        __stcs(o + 1, y);
        __stcs(o + 2, z);
        o += (size_t)TOUT * 3;   // next row
    }
}

// ---------------------------------------------------------------------------
// Launch. Inputs: d_in[0]=ctrl_pts [16,64,64,4] f32, d_in[1]=knot_u [16,68],
// d_in[2]=knot_v (UNUSED — reference builds V from knot_u).
// Output: [16,256,256,3] f32.
// ---------------------------------------------------------------------------
extern "C" void kernel_launch(void* const* d_in, const int* in_sizes, int n_in,
                              void* d_out, int out_size)
{
    const float4* ctrl   = (const float4*)d_in[0];
    const float*  knot_u = (const float*) d_in[1];
    float*        out    = (float*)d_out;

    SurfEval_fused_kernel<<<BATCH * BPB, THREADS>>>(ctrl, knot_u, out);
}